// round 1
// baseline (speedup 1.0000x reference)
#include <cuda_runtime.h>

#define NB 8192
#define NK 16
#define ND 512
#define NS 4

// ---------------- scratch (device globals: allocation-free) ----------------
__device__ float buf_ctx [(size_t)NB * ND];          // context        (B, D)
__device__ float buf_mkf [(size_t)NB * NK];          // float mask     (B, K)
__device__ float buf_h1  [(size_t)NB * 2 * ND];      // gelu(ctx@gw1)  (B, 2D)
__device__ float buf_ws  [(size_t)NB * NS * ND];     // workspace      (B, S, D)
__device__ float buf_qw  [(size_t)NB * NS * ND];     // ws @ wq
__device__ float buf_kw  [(size_t)NB * NK * ND];     // hidden @ wk
__device__ float buf_vw  [(size_t)NB * NK * ND];     // hidden @ wv
__device__ float buf_wsu [(size_t)NB * NS * ND];     // ws_upd
__device__ float buf_qr  [(size_t)NB * NK * ND];     // hidden @ rq
__device__ float buf_kr  [(size_t)NB * NS * ND];     // ws_upd @ rk
__device__ float buf_vr  [(size_t)NB * NS * ND];     // ws_upd @ rv
__device__ float buf_bc0 [(size_t)NB * NK * ND];     // attn_r @ Vr
__device__ float buf_bc  [(size_t)NB * NK * ND];     // bc0 @ ro

__device__ __forceinline__ float warp_sum(float v) {
    #pragma unroll
    for (int o = 16; o > 0; o >>= 1) v += __shfl_xor_sync(0xffffffffu, v, o);
    return v;
}

// ---------------- kernel 1: masked context pooling + mask normalize --------
// Auto-detects mask encoding: 1 = bool/uint8, 0 = int32, 2 = float32.
__global__ void ctx_kernel(const float* __restrict__ hidden, const void* mask_raw) {
    int b = blockIdx.x;
    int tid = threadIdx.x;                 // 512 threads, one per d
    __shared__ float sm[NK];
    __shared__ int smode;
    if (tid == 0) {
        const unsigned char* p = (const unsigned char*)mask_raw;
        int mode = 0;                      // default int32
        for (int i = 0; i < 512; ++i) {
            unsigned char v = p[i];
            if (!v) continue;
            if (v != 1u) { mode = 2; break; }      // 0x80 / 0x3f byte -> float32
            if (i & 3)   { mode = 1; break; }      // value-1 byte off word boundary -> bool
        }
        smode = mode;
    }
    __syncthreads();
    int mode = smode;
    if (tid < NK) {
        int idx = b * NK + tid;
        float m;
        if (mode == 1)      m = ((const unsigned char*)mask_raw)[idx] ? 1.f : 0.f;
        else if (mode == 0) m = ((const int*)mask_raw)[idx] ? 1.f : 0.f;
        else                m = ((const float*)mask_raw)[idx];
        sm[tid] = m;
        buf_mkf[idx] = m;
    }
    __syncthreads();
    float n = 0.f;
    #pragma unroll
    for (int k = 0; k < NK; ++k) n += sm[k];
    n = fmaxf(n, 1.f);
    float acc = 0.f;
    #pragma unroll
    for (int k = 0; k < NK; ++k)
        acc += sm[k] * hidden[((size_t)b * NK + k) * ND + tid];
    buf_ctx[(size_t)b * ND + tid] = acc / n;
}

// ---------------- generic tiled SGEMM: C = A(MxK) @ B(KxN) + epi -----------
// BM=BN=128, BK=16, 256 threads, 8x8 per-thread tile. All dims tile-divisible.
__global__ void __launch_bounds__(256, 2)
sgemm_kernel(const float* __restrict__ A, const float* __restrict__ B,
             float* __restrict__ C, int M, int N, int K,
             const float* __restrict__ bias1, const float* __restrict__ bias2,
             int do_gelu) {
    __shared__ float As[16][128];
    __shared__ float Bs[16][128];
    const int bm = blockIdx.y * 128;
    const int bn = blockIdx.x * 128;
    const int tid = threadIdx.x;
    const int tx = tid & 15;          // 16 cols of threads
    const int ty = tid >> 4;          // 16 rows of threads

    float acc[8][8];
    #pragma unroll
    for (int i = 0; i < 8; ++i)
        #pragma unroll
        for (int j = 0; j < 8; ++j) acc[i][j] = 0.f;

    const int arow = tid >> 2;               // 0..63
    const int acol = (tid & 3) * 4;          // 0,4,8,12
    const int brow = tid >> 5;               // 0..7
    const int bcol = (tid & 31) * 4;         // 0..124

    for (int k0 = 0; k0 < K; k0 += 16) {
        float4 a0 = *(const float4*)(A + (size_t)(bm + arow)      * K + k0 + acol);
        float4 a1 = *(const float4*)(A + (size_t)(bm + arow + 64) * K + k0 + acol);
        As[acol + 0][arow] = a0.x; As[acol + 1][arow] = a0.y;
        As[acol + 2][arow] = a0.z; As[acol + 3][arow] = a0.w;
        As[acol + 0][arow + 64] = a1.x; As[acol + 1][arow + 64] = a1.y;
        As[acol + 2][arow + 64] = a1.z; As[acol + 3][arow + 64] = a1.w;
        float4 b0 = *(const float4*)(B + (size_t)(k0 + brow)     * N + bn + bcol);
        float4 b1 = *(const float4*)(B + (size_t)(k0 + brow + 8) * N + bn + bcol);
        *(float4*)&Bs[brow][bcol]     = b0;
        *(float4*)&Bs[brow + 8][bcol] = b1;
        __syncthreads();

        #pragma unroll
        for (int kk = 0; kk < 16; ++kk) {
            float ar[8], br[8];
            #pragma unroll
            for (int i = 0; i < 8; ++i) ar[i] = As[kk][ty * 8 + i];
            #pragma unroll
            for (int j = 0; j < 8; ++j) br[j] = Bs[kk][tx * 8 + j];
            #pragma unroll
            for (int i = 0; i < 8; ++i)
                #pragma unroll
                for (int j = 0; j < 8; ++j)
                    acc[i][j] = fmaf(ar[i], br[j], acc[i][j]);
        }
        __syncthreads();
    }

    #pragma unroll
    for (int i = 0; i < 8; ++i) {
        const size_t row = (size_t)(bm + ty * 8 + i);
        float out[8];
        #pragma unroll
        for (int j = 0; j < 8; ++j) {
            int col = bn + tx * 8 + j;
            float v = acc[i][j];
            if (bias1) v += bias1[col];
            if (bias2) v += bias2[col];
            if (do_gelu) v = 0.5f * v * (1.f + erff(v * 0.70710678118654752f));
            out[j] = v;
        }
        float4* cp = (float4*)(C + row * N + bn + tx * 8);
        cp[0] = make_float4(out[0], out[1], out[2], out[3]);
        cp[1] = make_float4(out[4], out[5], out[6], out[7]);
    }
}

// ---------------- kernel: attention #1 (ws queries hidden) + LN ------------
// One CTA per batch, 4 warps; warp s owns workspace slot s.
__global__ void attn1_kernel(const float* __restrict__ gamma,
                             const float* __restrict__ beta) {
    const int b = blockIdx.x;
    const int warp = threadIdx.x >> 5;
    const int lane = threadIdx.x & 31;
    const int s = warp;
    const float scale = 0.04419417382415922f;   // 1/sqrt(512)

    const float* q = buf_qw + ((size_t)b * NS + s) * ND;
    float lg[NK];
    #pragma unroll
    for (int k = 0; k < NK; ++k) {
        const float* kw = buf_kw + ((size_t)b * NK + k) * ND;
        float part = 0.f;
        for (int d = lane; d < ND; d += 32) part += q[d] * kw[d];
        part = warp_sum(part);
        float m = buf_mkf[b * NK + k];
        lg[k] = (m > 0.5f) ? part * scale : -1e30f;
    }
    float mx = -1e30f;
    #pragma unroll
    for (int k = 0; k < NK; ++k) mx = fmaxf(mx, lg[k]);
    float den = 0.f;
    #pragma unroll
    for (int k = 0; k < NK; ++k) { lg[k] = expf(lg[k] - mx); den += lg[k]; }
    const float inv = 1.f / den;

    float y[16];
    #pragma unroll
    for (int t = 0; t < 16; ++t) {
        int d = lane + 32 * t;
        float o = 0.f;
        #pragma unroll
        for (int k = 0; k < NK; ++k)
            o = fmaf(lg[k], buf_vw[((size_t)b * NK + k) * ND + d], o);
        y[t] = buf_ws[((size_t)b * NS + s) * ND + d] + o * inv;
    }
    float sum = 0.f;
    #pragma unroll
    for (int t = 0; t < 16; ++t) sum += y[t];
    const float mu = warp_sum(sum) * (1.f / ND);
    float sq = 0.f;
    #pragma unroll
    for (int t = 0; t < 16; ++t) { float c = y[t] - mu; sq += c * c; }
    const float var = warp_sum(sq) * (1.f / ND);
    const float rstd = rsqrtf(var + 1e-5f);
    #pragma unroll
    for (int t = 0; t < 16; ++t) {
        int d = lane + 32 * t;
        buf_wsu[((size_t)b * NS + s) * ND + d] = (y[t] - mu) * rstd * gamma[d] + beta[d];
    }
}

// ---------------- kernel: attention #2 (hidden queries ws_upd) -------------
// One CTA per batch, 16 warps; warp k owns token k.
__global__ void attn2_kernel() {
    const int b = blockIdx.x;
    const int warp = threadIdx.x >> 5;
    const int lane = threadIdx.x & 31;
    const int k = warp;
    const float scale = 0.04419417382415922f;

    const float* q = buf_qr + ((size_t)b * NK + k) * ND;
    float lg[NS];
    #pragma unroll
    for (int s = 0; s < NS; ++s) {
        const float* kr = buf_kr + ((size_t)b * NS + s) * ND;
        float part = 0.f;
        for (int d = lane; d < ND; d += 32) part += q[d] * kr[d];
        lg[s] = warp_sum(part) * scale;
    }
    float mx = -1e30f;
    #pragma unroll
    for (int s = 0; s < NS; ++s) mx = fmaxf(mx, lg[s]);
    float den = 0.f;
    #pragma unroll
    for (int s = 0; s < NS; ++s) { lg[s] = expf(lg[s] - mx); den += lg[s]; }
    const float inv = 1.f / den;

    #pragma unroll
    for (int t = 0; t < 16; ++t) {
        int d = lane + 32 * t;
        float o = 0.f;
        #pragma unroll
        for (int s = 0; s < NS; ++s)
            o = fmaf(lg[s], buf_vr[((size_t)b * NS + s) * ND + d], o);
        buf_bc0[((size_t)b * NK + k) * ND + d] = o * inv;
    }
}

// ---------------- kernel: final residual + layernorm ----------------------
// 8 warps/CTA, one row (b,k) per warp.
__global__ void lnout_kernel(const float* __restrict__ hidden,
                             const float* __restrict__ gamma,
                             const float* __restrict__ beta,
                             float* __restrict__ out) {
    const int row = blockIdx.x * 8 + (threadIdx.x >> 5);
    const int lane = threadIdx.x & 31;
    float y[16];
    #pragma unroll
    for (int t = 0; t < 16; ++t) {
        int d = lane + 32 * t;
        y[t] = hidden[(size_t)row * ND + d] + buf_bc[(size_t)row * ND + d];
    }
    float sum = 0.f;
    #pragma unroll
    for (int t = 0; t < 16; ++t) sum += y[t];
    const float mu = warp_sum(sum) * (1.f / ND);
    float sq = 0.f;
    #pragma unroll
    for (int t = 0; t < 16; ++t) { float c = y[t] - mu; sq += c * c; }
    const float var = warp_sum(sq) * (1.f / ND);
    const float rstd = rsqrtf(var + 1e-5f);
    #pragma unroll
    for (int t = 0; t < 16; ++t) {
        int d = lane + 32 * t;
        out[(size_t)row * ND + d] = (y[t] - mu) * rstd * gamma[d] + beta[d];
    }
}

// ---------------- host launcher --------------------------------------------
extern "C" void kernel_launch(void* const* d_in, const int* in_sizes, int n_in,
                              void* d_out, int out_size) {
    const float* hidden   = (const float*)d_in[0];
    const void*  mask     = d_in[1];
    const float* fallback = (const float*)d_in[2];
    const float* gw1      = (const float*)d_in[3];
    const float* gb1      = (const float*)d_in[4];
    const float* gw2      = (const float*)d_in[5];
    const float* gb2      = (const float*)d_in[6];
    const float* wq       = (const float*)d_in[7];
    const float* wk       = (const float*)d_in[8];
    const float* wv       = (const float*)d_in[9];
    const float* rq       = (const float*)d_in[10];
    const float* rk       = (const float*)d_in[11];
    const float* rv       = (const float*)d_in[12];
    const float* ro       = (const float*)d_in[13];
    const float* g_ws_w   = (const float*)d_in[14];
    const float* b_ws_w   = (const float*)d_in[15];
    const float* g_out_w  = (const float*)d_in[16];
    const float* b_out_w  = (const float*)d_in[17];
    float* out = (float*)d_out;

    float *ctx, *h1, *ws, *qw, *kw, *vw, *wsu, *qr, *kr, *vr, *bc0, *bc;
    cudaGetSymbolAddress((void**)&ctx, buf_ctx);
    cudaGetSymbolAddress((void**)&h1,  buf_h1);
    cudaGetSymbolAddress((void**)&ws,  buf_ws);
    cudaGetSymbolAddress((void**)&qw,  buf_qw);
    cudaGetSymbolAddress((void**)&kw,  buf_kw);
    cudaGetSymbolAddress((void**)&vw,  buf_vw);
    cudaGetSymbolAddress((void**)&wsu, buf_wsu);
    cudaGetSymbolAddress((void**)&qr,  buf_qr);
    cudaGetSymbolAddress((void**)&kr,  buf_kr);
    cudaGetSymbolAddress((void**)&vr,  buf_vr);
    cudaGetSymbolAddress((void**)&bc0, buf_bc0);
    cudaGetSymbolAddress((void**)&bc,  buf_bc);

    // 1) context pooling (+ mask decode)
    ctx_kernel<<<NB, ND>>>(hidden, mask);

    // 2) h1 = gelu(ctx @ gw1 + gb1)            (8192 x 1024, K=512)
    sgemm_kernel<<<dim3(1024/128, 8192/128), 256>>>(ctx, gw1, h1, 8192, 1024, 512,
                                                    gb1, nullptr, 1);
    // 3) ws = h1 @ gw2 + gb2 + fallback        (8192 x 2048, K=1024)
    sgemm_kernel<<<dim3(2048/128, 8192/128), 256>>>(h1, gw2, ws, 8192, 2048, 1024,
                                                    gb2, fallback, 0);
    // 4) Qw = ws @ wq                          (32768 x 512, K=512)
    sgemm_kernel<<<dim3(512/128, 32768/128), 256>>>(ws, wq, qw, 32768, 512, 512,
                                                    nullptr, nullptr, 0);
    // 5) Kw = hidden @ wk ; Vw = hidden @ wv   (131072 x 512, K=512)
    sgemm_kernel<<<dim3(512/128, 131072/128), 256>>>(hidden, wk, kw, 131072, 512, 512,
                                                     nullptr, nullptr, 0);
    sgemm_kernel<<<dim3(512/128, 131072/128), 256>>>(hidden, wv, vw, 131072, 512, 512,
                                                     nullptr, nullptr, 0);
    // 6) attention #1 + layernorm -> ws_upd
    attn1_kernel<<<NB, 128>>>(g_ws_w, b_ws_w);

    // 7) Qr = hidden @ rq                      (131072 x 512)
    sgemm_kernel<<<dim3(512/128, 131072/128), 256>>>(hidden, rq, qr, 131072, 512, 512,
                                                     nullptr, nullptr, 0);
    // 8) Kr = ws_upd @ rk ; Vr = ws_upd @ rv   (32768 x 512)
    sgemm_kernel<<<dim3(512/128, 32768/128), 256>>>(wsu, rk, kr, 32768, 512, 512,
                                                    nullptr, nullptr, 0);
    sgemm_kernel<<<dim3(512/128, 32768/128), 256>>>(wsu, rv, vr, 32768, 512, 512,
                                                    nullptr, nullptr, 0);
    // 9) attention #2 -> bc0
    attn2_kernel<<<NB, 512>>>();

    // 10) bc = bc0 @ ro                        (131072 x 512)
    sgemm_kernel<<<dim3(512/128, 131072/128), 256>>>(bc0, ro, bc, 131072, 512, 512,
                                                     nullptr, nullptr, 0);
    // 11) out = layernorm(hidden + bc)
    lnout_kernel<<<(NB * NK) / 8, 256>>>(hidden, g_out_w, b_out_w, out);
}

// round 2
// speedup vs baseline: 2.1821x; 2.1821x over previous
#include <cuda_runtime.h>

#define NB 8192
#define NK 16
#define ND 512
#define NS 4

// ---------------- scratch (device globals: allocation-free) ----------------
__device__ float buf_ctx [(size_t)NB * ND];
__device__ float buf_mkf [(size_t)NB * NK];
__device__ float buf_h1  [(size_t)NB * 2 * ND];
__device__ float buf_ws  [(size_t)NB * NS * ND];
__device__ float buf_qw  [(size_t)NB * NS * ND];
__device__ float buf_kw  [(size_t)NB * NK * ND];
__device__ float buf_vw  [(size_t)NB * NK * ND];
__device__ float buf_wsu [(size_t)NB * NS * ND];
__device__ float buf_qr  [(size_t)NB * NK * ND];
__device__ float buf_kr  [(size_t)NB * NS * ND];
__device__ float buf_vr  [(size_t)NB * NS * ND];
__device__ float buf_bc0 [(size_t)NB * NK * ND];
__device__ float buf_bc  [(size_t)NB * NK * ND];

__device__ __forceinline__ float warp_sum(float v) {
    #pragma unroll
    for (int o = 16; o > 0; o >>= 1) v += __shfl_xor_sync(0xffffffffu, v, o);
    return v;
}

__device__ __forceinline__ float f2tf32(float f) {
    unsigned r;
    asm("cvt.rna.tf32.f32 %0, %1;" : "=r"(r) : "f"(f));
    return __uint_as_float(r);
}

__device__ __forceinline__ void mma_tf32(float c[4], const unsigned a[4], const unsigned b[2]) {
    asm volatile(
        "mma.sync.aligned.m16n8k8.row.col.f32.tf32.tf32.f32 "
        "{%0,%1,%2,%3}, {%4,%5,%6,%7}, {%8,%9}, {%0,%1,%2,%3};"
        : "+f"(c[0]), "+f"(c[1]), "+f"(c[2]), "+f"(c[3])
        : "r"(a[0]), "r"(a[1]), "r"(a[2]), "r"(a[3]), "r"(b[0]), "r"(b[1]));
}

// ---------------- kernel 1: masked context pooling + mask normalize --------
__global__ void ctx_kernel(const float* __restrict__ hidden, const void* mask_raw) {
    int b = blockIdx.x;
    int tid = threadIdx.x;
    __shared__ float sm[NK];
    __shared__ int smode;
    if (tid == 0) {
        const unsigned char* p = (const unsigned char*)mask_raw;
        int mode = 0;
        for (int i = 0; i < 512; ++i) {
            unsigned char v = p[i];
            if (!v) continue;
            if (v != 1u) { mode = 2; break; }
            if (i & 3)   { mode = 1; break; }
        }
        smode = mode;
    }
    __syncthreads();
    int mode = smode;
    if (tid < NK) {
        int idx = b * NK + tid;
        float m;
        if (mode == 1)      m = ((const unsigned char*)mask_raw)[idx] ? 1.f : 0.f;
        else if (mode == 0) m = ((const int*)mask_raw)[idx] ? 1.f : 0.f;
        else                m = ((const float*)mask_raw)[idx];
        sm[tid] = m;
        buf_mkf[idx] = m;
    }
    __syncthreads();
    float n = 0.f;
    #pragma unroll
    for (int k = 0; k < NK; ++k) n += sm[k];
    n = fmaxf(n, 1.f);
    float acc = 0.f;
    #pragma unroll
    for (int k = 0; k < NK; ++k)
        acc += sm[k] * hidden[((size_t)b * NK + k) * ND + tid];
    buf_ctx[(size_t)b * ND + tid] = acc / n;
}

// ---------------- TF32 tensor-core SGEMM: C = A(MxK) @ B(KxN) + epi --------
// 128x128 CTA tile, BK=16, 256 threads = 8 warps (2x4), 64x32 warp tile.
// Double-buffered smem, stride-136 padding (conflict-free fragment loads).
#define SSTR 136
__global__ void __launch_bounds__(256, 2)
sgemm_tc(const float* __restrict__ A, const float* __restrict__ B,
         float* __restrict__ C, int M, int N, int K,
         const float* __restrict__ bias1, const float* __restrict__ bias2,
         int do_gelu) {
    __shared__ float As[2][16][SSTR];
    __shared__ float Bs[2][16][SSTR];

    const int bm = blockIdx.y * 128;
    const int bn = blockIdx.x * 128;
    const int tid  = threadIdx.x;
    const int warp = tid >> 5;
    const int lane = tid & 31;
    const int gid  = lane >> 2;      // groupID 0..7
    const int tig  = lane & 3;       // thread-in-group 0..3
    const int wm   = (warp >> 2) * 64;   // warp m offset (0/64)
    const int wn   = (warp & 3) * 32;    // warp n offset (0..96)

    const int arow = tid >> 2;            // 0..63
    const int acol = (tid & 3) * 4;       // 0,4,8,12
    const int brow = tid >> 5;            // 0..7
    const int bcol = (tid & 31) * 4;      // 0..124

    float acc[4][4][4];
    #pragma unroll
    for (int i = 0; i < 4; ++i)
        #pragma unroll
        for (int j = 0; j < 4; ++j)
            #pragma unroll
            for (int r = 0; r < 4; ++r) acc[i][j][r] = 0.f;

    const int nk = K >> 4;

    // fill stage: global -> smem (with TF32 rounding)
    auto fill = [&](int st, int k0) {
        float4 a0 = *(const float4*)(A + (size_t)(bm + arow)      * K + k0 + acol);
        float4 a1 = *(const float4*)(A + (size_t)(bm + arow + 64) * K + k0 + acol);
        As[st][acol + 0][arow] = f2tf32(a0.x); As[st][acol + 1][arow] = f2tf32(a0.y);
        As[st][acol + 2][arow] = f2tf32(a0.z); As[st][acol + 3][arow] = f2tf32(a0.w);
        As[st][acol + 0][arow + 64] = f2tf32(a1.x); As[st][acol + 1][arow + 64] = f2tf32(a1.y);
        As[st][acol + 2][arow + 64] = f2tf32(a1.z); As[st][acol + 3][arow + 64] = f2tf32(a1.w);
        float4 b0 = *(const float4*)(B + (size_t)(k0 + brow)     * N + bn + bcol);
        float4 b1 = *(const float4*)(B + (size_t)(k0 + brow + 8) * N + bn + bcol);
        Bs[st][brow][bcol + 0] = f2tf32(b0.x); Bs[st][brow][bcol + 1] = f2tf32(b0.y);
        Bs[st][brow][bcol + 2] = f2tf32(b0.z); Bs[st][brow][bcol + 3] = f2tf32(b0.w);
        Bs[st][brow + 8][bcol + 0] = f2tf32(b1.x); Bs[st][brow + 8][bcol + 1] = f2tf32(b1.y);
        Bs[st][brow + 8][bcol + 2] = f2tf32(b1.z); Bs[st][brow + 8][bcol + 3] = f2tf32(b1.w);
    };

    fill(0, 0);
    __syncthreads();

    for (int kt = 0; kt < nk; ++kt) {
        const int st = kt & 1;
        if (kt + 1 < nk) fill((kt + 1) & 1, (kt + 1) << 4);

        #pragma unroll
        for (int kc = 0; kc < 2; ++kc) {
            const int kb = kc * 8;
            unsigned bfr[4][2];
            #pragma unroll
            for (int j = 0; j < 4; ++j) {
                const int col = wn + j * 8 + gid;
                bfr[j][0] = __float_as_uint(Bs[st][kb + tig][col]);
                bfr[j][1] = __float_as_uint(Bs[st][kb + tig + 4][col]);
            }
            #pragma unroll
            for (int i = 0; i < 4; ++i) {
                const int row = wm + i * 16 + gid;
                unsigned afr[4];
                afr[0] = __float_as_uint(As[st][kb + tig][row]);
                afr[1] = __float_as_uint(As[st][kb + tig][row + 8]);
                afr[2] = __float_as_uint(As[st][kb + tig + 4][row]);
                afr[3] = __float_as_uint(As[st][kb + tig + 4][row + 8]);
                #pragma unroll
                for (int j = 0; j < 4; ++j)
                    mma_tf32(acc[i][j], afr, bfr[j]);
            }
        }
        __syncthreads();
    }

    // epilogue
    #pragma unroll
    for (int i = 0; i < 4; ++i) {
        #pragma unroll
        for (int j = 0; j < 4; ++j) {
            #pragma unroll
            for (int half = 0; half < 2; ++half) {
                const int row = bm + wm + i * 16 + gid + half * 8;
                const int col = bn + wn + j * 8 + tig * 2;
                float v0 = acc[i][j][half * 2 + 0];
                float v1 = acc[i][j][half * 2 + 1];
                if (bias1) { v0 += bias1[col]; v1 += bias1[col + 1]; }
                if (bias2) { v0 += bias2[col]; v1 += bias2[col + 1]; }
                if (do_gelu) {
                    v0 = 0.5f * v0 * (1.f + erff(v0 * 0.70710678118654752f));
                    v1 = 0.5f * v1 * (1.f + erff(v1 * 0.70710678118654752f));
                }
                *(float2*)(C + (size_t)row * N + col) = make_float2(v0, v1);
            }
        }
    }
}

// ---------------- kernel: attention #1 (ws queries hidden) + LN ------------
__global__ void attn1_kernel(const float* __restrict__ gamma,
                             const float* __restrict__ beta) {
    const int b = blockIdx.x;
    const int warp = threadIdx.x >> 5;
    const int lane = threadIdx.x & 31;
    const int s = warp;
    const float scale = 0.04419417382415922f;

    const float* q = buf_qw + ((size_t)b * NS + s) * ND;
    float lg[NK];
    #pragma unroll
    for (int k = 0; k < NK; ++k) {
        const float* kw = buf_kw + ((size_t)b * NK + k) * ND;
        float part = 0.f;
        for (int d = lane; d < ND; d += 32) part += q[d] * kw[d];
        part = warp_sum(part);
        float m = buf_mkf[b * NK + k];
        lg[k] = (m > 0.5f) ? part * scale : -1e30f;
    }
    float mx = -1e30f;
    #pragma unroll
    for (int k = 0; k < NK; ++k) mx = fmaxf(mx, lg[k]);
    float den = 0.f;
    #pragma unroll
    for (int k = 0; k < NK; ++k) { lg[k] = expf(lg[k] - mx); den += lg[k]; }
    const float inv = 1.f / den;

    float y[16];
    #pragma unroll
    for (int t = 0; t < 16; ++t) {
        int d = lane + 32 * t;
        float o = 0.f;
        #pragma unroll
        for (int k = 0; k < NK; ++k)
            o = fmaf(lg[k], buf_vw[((size_t)b * NK + k) * ND + d], o);
        y[t] = buf_ws[((size_t)b * NS + s) * ND + d] + o * inv;
    }
    float sum = 0.f;
    #pragma unroll
    for (int t = 0; t < 16; ++t) sum += y[t];
    const float mu = warp_sum(sum) * (1.f / ND);
    float sq = 0.f;
    #pragma unroll
    for (int t = 0; t < 16; ++t) { float c = y[t] - mu; sq += c * c; }
    const float var = warp_sum(sq) * (1.f / ND);
    const float rstd = rsqrtf(var + 1e-5f);
    #pragma unroll
    for (int t = 0; t < 16; ++t) {
        int d = lane + 32 * t;
        buf_wsu[((size_t)b * NS + s) * ND + d] = (y[t] - mu) * rstd * gamma[d] + beta[d];
    }
}

// ---------------- kernel: attention #2 (hidden queries ws_upd) -------------
__global__ void attn2_kernel() {
    const int b = blockIdx.x;
    const int warp = threadIdx.x >> 5;
    const int lane = threadIdx.x & 31;
    const int k = warp;
    const float scale = 0.04419417382415922f;

    const float* q = buf_qr + ((size_t)b * NK + k) * ND;
    float lg[NS];
    #pragma unroll
    for (int s = 0; s < NS; ++s) {
        const float* kr = buf_kr + ((size_t)b * NS + s) * ND;
        float part = 0.f;
        for (int d = lane; d < ND; d += 32) part += q[d] * kr[d];
        lg[s] = warp_sum(part) * scale;
    }
    float mx = -1e30f;
    #pragma unroll
    for (int s = 0; s < NS; ++s) mx = fmaxf(mx, lg[s]);
    float den = 0.f;
    #pragma unroll
    for (int s = 0; s < NS; ++s) { lg[s] = expf(lg[s] - mx); den += lg[s]; }
    const float inv = 1.f / den;

    #pragma unroll
    for (int t = 0; t < 16; ++t) {
        int d = lane + 32 * t;
        float o = 0.f;
        #pragma unroll
        for (int s = 0; s < NS; ++s)
            o = fmaf(lg[s], buf_vr[((size_t)b * NS + s) * ND + d], o);
        buf_bc0[((size_t)b * NK + k) * ND + d] = o * inv;
    }
}

// ---------------- kernel: final residual + layernorm ----------------------
__global__ void lnout_kernel(const float* __restrict__ hidden,
                             const float* __restrict__ gamma,
                             const float* __restrict__ beta,
                             float* __restrict__ out) {
    const int row = blockIdx.x * 8 + (threadIdx.x >> 5);
    const int lane = threadIdx.x & 31;
    float y[16];
    #pragma unroll
    for (int t = 0; t < 16; ++t) {
        int d = lane + 32 * t;
        y[t] = hidden[(size_t)row * ND + d] + buf_bc[(size_t)row * ND + d];
    }
    float sum = 0.f;
    #pragma unroll
    for (int t = 0; t < 16; ++t) sum += y[t];
    const float mu = warp_sum(sum) * (1.f / ND);
    float sq = 0.f;
    #pragma unroll
    for (int t = 0; t < 16; ++t) { float c = y[t] - mu; sq += c * c; }
    const float var = warp_sum(sq) * (1.f / ND);
    const float rstd = rsqrtf(var + 1e-5f);
    #pragma unroll
    for (int t = 0; t < 16; ++t) {
        int d = lane + 32 * t;
        out[(size_t)row * ND + d] = (y[t] - mu) * rstd * gamma[d] + beta[d];
    }
}

// ---------------- host launcher --------------------------------------------
extern "C" void kernel_launch(void* const* d_in, const int* in_sizes, int n_in,
                              void* d_out, int out_size) {
    const float* hidden   = (const float*)d_in[0];
    const void*  mask     = d_in[1];
    const float* fallback = (const float*)d_in[2];
    const float* gw1      = (const float*)d_in[3];
    const float* gb1      = (const float*)d_in[4];
    const float* gw2      = (const float*)d_in[5];
    const float* gb2      = (const float*)d_in[6];
    const float* wq       = (const float*)d_in[7];
    const float* wk       = (const float*)d_in[8];
    const float* wv       = (const float*)d_in[9];
    const float* rq       = (const float*)d_in[10];
    const float* rk       = (const float*)d_in[11];
    const float* rv       = (const float*)d_in[12];
    const float* ro       = (const float*)d_in[13];
    const float* g_ws_w   = (const float*)d_in[14];
    const float* b_ws_w   = (const float*)d_in[15];
    const float* g_out_w  = (const float*)d_in[16];
    const float* b_out_w  = (const float*)d_in[17];
    float* out = (float*)d_out;

    float *ctx, *h1, *ws, *qw, *kw, *vw, *wsu, *qr, *kr, *vr, *bc0, *bc;
    cudaGetSymbolAddress((void**)&ctx, buf_ctx);
    cudaGetSymbolAddress((void**)&h1,  buf_h1);
    cudaGetSymbolAddress((void**)&ws,  buf_ws);
    cudaGetSymbolAddress((void**)&qw,  buf_qw);
    cudaGetSymbolAddress((void**)&kw,  buf_kw);
    cudaGetSymbolAddress((void**)&vw,  buf_vw);
    cudaGetSymbolAddress((void**)&wsu, buf_wsu);
    cudaGetSymbolAddress((void**)&qr,  buf_qr);
    cudaGetSymbolAddress((void**)&kr,  buf_kr);
    cudaGetSymbolAddress((void**)&vr,  buf_vr);
    cudaGetSymbolAddress((void**)&bc0, buf_bc0);
    cudaGetSymbolAddress((void**)&bc,  buf_bc);

    ctx_kernel<<<NB, ND>>>(hidden, mask);

    sgemm_tc<<<dim3(1024/128, 8192/128), 256>>>(ctx, gw1, h1, 8192, 1024, 512,
                                                gb1, nullptr, 1);
    sgemm_tc<<<dim3(2048/128, 8192/128), 256>>>(h1, gw2, ws, 8192, 2048, 1024,
                                                gb2, fallback, 0);
    sgemm_tc<<<dim3(512/128, 32768/128), 256>>>(ws, wq, qw, 32768, 512, 512,
                                                nullptr, nullptr, 0);
    sgemm_tc<<<dim3(512/128, 131072/128), 256>>>(hidden, wk, kw, 131072, 512, 512,
                                                 nullptr, nullptr, 0);
    sgemm_tc<<<dim3(512/128, 131072/128), 256>>>(hidden, wv, vw, 131072, 512, 512,
                                                 nullptr, nullptr, 0);
    attn1_kernel<<<NB, 128>>>(g_ws_w, b_ws_w);

    sgemm_tc<<<dim3(512/128, 131072/128), 256>>>(hidden, rq, qr, 131072, 512, 512,
                                                 nullptr, nullptr, 0);
    sgemm_tc<<<dim3(512/128, 32768/128), 256>>>(wsu, rk, kr, 32768, 512, 512,
                                                nullptr, nullptr, 0);
    sgemm_tc<<<dim3(512/128, 32768/128), 256>>>(wsu, rv, vr, 32768, 512, 512,
                                                nullptr, nullptr, 0);
    attn2_kernel<<<NB, 512>>>();

    sgemm_tc<<<dim3(512/128, 131072/128), 256>>>(bc0, ro, bc, 131072, 512, 512,
                                                 nullptr, nullptr, 0);
    lnout_kernel<<<(NB * NK) / 8, 256>>>(hidden, g_out_w, b_out_w, out);
}